// round 15
// baseline (speedup 1.0000x reference)
#include <cuda_runtime.h>
#include <cstdint>

#define NMAXN   131072
#define EMAXE   2200000
#define PMAXP   32768
#define CMAXC   256
#define BMAXB   64
#define HBITS   20
#define HSIZE   (1u << HBITS)
#define PAIRMAX 2097152
#define HEMPTY  0xFFFFFFFFFFFFFFFFull
#define VUNSET  0xFFFFFFFFFFFFFFFFull
#define MAXPROBE 128
#define GFT     512
typedef unsigned long long u64;

__device__ float    g_z[NMAXN];
__device__ float    g_e[NMAXN];          // exp -> normalized elev after k_pre
__device__ int      g_notpeak[NMAXN];
__device__ u64      g_visitcl[NMAXN];    // (level<<32)|cluster of first claim
__device__ int      g_outdeg[NMAXN];
__device__ int      g_rowoff[NMAXN + 1];
__device__ int      g_fillpos[NMAXN];
__device__ int      g_peakrank[NMAXN];
__device__ int      g_col[EMAXE];
__device__ uint2    g_desc[EMAXE];
__device__ uint4    g_pairs[PAIRMAX];    // (v, c, rowbeg, rowend)
__device__ int      g_mlist[PAIRMAX];
__device__ u64      g_htab[HSIZE];
__device__ float4   g_pool4[(size_t)PMAXP * CMAXC / 4];
__device__ float    g_maxelevF[PMAXP];
__device__ int      g_cbv[PMAXP];
__device__ float    g_exn[PMAXP];
__device__ int      g_ccount[PMAXP];
__device__ int      g_cc2[PMAXP];
__device__ int      g_rowP[PMAXP + 1];
__device__ unsigned g_bmaxz[BMAXB];
__device__ float    g_bsum[BMAXB];
__device__ unsigned g_cbmax[BMAXB];
__device__ float    g_cbsum[BMAXB];
__device__ int      g_bsA[1024];
__device__ int      g_bsB[1024];
__device__ int      g_nP;
__device__ int      g_is64;
__device__ int      g_desc_tail;
__device__ int      g_ptail;

struct Bar { int cnt; int gen; int snap; };
__device__ Bar g_barA;
__device__ Bar g_barB;

// ---------------- helpers ----------------
__device__ __forceinline__ unsigned encf(float f) {
    unsigned u = __float_as_uint(f);
    return (u & 0x80000000u) ? ~u : (u | 0x80000000u);
}
__device__ __forceinline__ float decf(unsigned u) {
    return __uint_as_float((u & 0x80000000u) ? (u ^ 0x80000000u) : ~u);
}
__device__ __forceinline__ long long ld_idx(const void* p, long long i, int is64) {
    if (is64) return ((const long long*)p)[i];
    return (long long)((const int*)p)[i];
}
__device__ __forceinline__ void gbar(Bar* b) {
    __syncthreads();
    if (threadIdx.x == 0) {
        __threadfence();
        volatile int* vg = &b->gen;
        int g = *vg;
        if (atomicAdd(&b->cnt, 1) == (int)gridDim.x - 1) {
            b->cnt = 0;
            __threadfence();
            atomicExch(&b->gen, g + 1);
        } else {
            int it = 0;
            while (*vg == g) { if (++it > 4096) { __nanosleep(128); it = 2048; } }
        }
        __threadfence();
    }
    __syncthreads();
}
// barrier + snapshot of g_ptail taken by the releasing block
__device__ __forceinline__ int gbar_snap(Bar* b) {
    __shared__ int s_hi;
    __syncthreads();
    if (threadIdx.x == 0) {
        __threadfence();
        volatile int* vg = &b->gen;
        volatile int* vs = &b->snap;
        int g = *vg;
        if (atomicAdd(&b->cnt, 1) == (int)gridDim.x - 1) {
            int nt = g_ptail; if (nt > PAIRMAX) nt = PAIRMAX;
            *vs = nt;
            b->cnt = 0;
            __threadfence();
            atomicExch(&b->gen, g + 1);
            s_hi = nt;
        } else {
            int it = 0;
            while (*vg == g) { if (++it > 4096) { __nanosleep(128); it = 2048; } }
            __threadfence();
            s_hi = *vs;
        }
        __threadfence();
    }
    __syncthreads();
    return s_hi;
}

// ---------------- L1: init clears + sniff + z + per-batch max ----------------
__global__ void k_initz(const float* __restrict__ x, const float* __restrict__ W,
                        const float* __restrict__ bb, const void* batch,
                        const void* ei, int N, int C, int E) {
    __shared__ unsigned s_bmax[BMAXB];
    __shared__ int s_is64;
    int tid = threadIdx.x;
    if (tid < 32) {
        int nch = E < 8 ? E : 8;
        bool bad = false;
        if (tid < nch) {
            long long v = ((const long long*)ei)[tid];
            bad = (v < 0 || v >= (long long)N);
        }
        unsigned m = __ballot_sync(0xffffffffu, bad);
        if (tid == 0) s_is64 = (m == 0) ? 1 : 0;
    }
    if (tid < BMAXB) s_bmax[tid] = 0u;
    __syncthreads();
    int is64 = s_is64;
    size_t t = (size_t)blockIdx.x * blockDim.x + tid;
    size_t stride = (size_t)gridDim.x * blockDim.x;
    for (size_t i = t; i < HSIZE; i += stride) g_htab[i] = HEMPTY;
    for (size_t i = t; i < (size_t)N; i += stride) {
        g_visitcl[i] = VUNSET; g_notpeak[i] = 0; g_outdeg[i] = 0; g_fillpos[i] = 0;
    }
    for (size_t i = t; i < PMAXP; i += stride) { g_ccount[i] = 0; g_cc2[i] = 0; }
    if (t < BMAXB) { g_bmaxz[t] = 0u; g_bsum[t] = 0.f; g_cbmax[t] = 0u; g_cbsum[t] = 0.f; }
    if (t == 0) {
        g_desc_tail = 0;
        g_barA.cnt = 0; g_barA.gen = 0; g_barA.snap = 0;
        g_barB.cnt = 0; g_barB.gen = 0; g_barB.snap = 0;
        g_is64 = is64;
    }
    // z = x @ W^T + b, warp per node
    int gw = (int)(((size_t)blockIdx.x * blockDim.x + tid) >> 5);
    int lane = tid & 31;
    int nw = (int)(((size_t)gridDim.x * blockDim.x) >> 5);
    int C4 = (C % 4 == 0) ? (C >> 2) : 0;
    for (int n = gw; n < N; n += nw) {
        float acc = 0.f;
        if (C4) {
            const float4* xr = (const float4*)(x + (size_t)n * C);
            const float4* wr = (const float4*)W;
            for (int i = lane; i < C4; i += 32) {
                float4 a = xr[i], w = wr[i];
                acc += a.x * w.x + a.y * w.y + a.z * w.z + a.w * w.w;
            }
        } else {
            for (int i = lane; i < C; i += 32) acc += x[(size_t)n * C + i] * W[i];
        }
        double d = (double)acc;
        #pragma unroll
        for (int o = 16; o; o >>= 1) d += __shfl_down_sync(0xffffffffu, d, o);
        if (lane == 0) {
            float zf = (float)d + bb[0];
            g_z[n] = zf;
            long long bt = ld_idx(batch, n, is64);
            if (bt >= 0 && bt < BMAXB) atomicMax(&s_bmax[bt], encf(zf));
        }
    }
    __syncthreads();
    if (tid < BMAXB && s_bmax[tid] != 0u) atomicMax(&g_bmaxz[tid], s_bmax[tid]);
}

// ---------------- L2: exp + batch sums + peak flags + descending edge list ----------------
__global__ void k_ee(const void* ei, const void* batch, int N, int E) {
    __shared__ float ssum[BMAXB];
    int tid = threadIdx.x;
    if (tid < BMAXB) ssum[tid] = 0.f;
    __syncthreads();
    int is64 = g_is64;
    int stride = gridDim.x * blockDim.x;
    for (int n = blockIdx.x * blockDim.x + tid; n < N; n += stride) {
        long long bt = ld_idx(batch, n, is64);
        float ev = expf(g_z[n] - decf(g_bmaxz[bt]));
        g_e[n] = ev;
        atomicAdd(&ssum[bt], ev);
    }
    __syncthreads();
    if (tid < BMAXB && ssum[tid] != 0.f) atomicAdd(&g_bsum[tid], ssum[tid]);
    for (int e = blockIdx.x * blockDim.x + tid; e < E; e += stride) {
        int ls = (int)ld_idx(ei, e, is64);
        int ld = (int)ld_idx(ei, (long long)E + e, is64);
        float zs = g_z[ls], zd = g_z[ld];
        if (zd < zs) g_notpeak[ld] = 1;
        bool desc = (zd <= zs);
        unsigned m = __ballot_sync(__activemask(), desc);
        if (desc) {
            int lane = tid & 31;
            int leader = __ffs(m) - 1;
            int base = 0;
            if (lane == leader) base = atomicAdd(&g_desc_tail, __popc(m));
            base = __shfl_sync(m, base, leader);
            int pos = base + __popc(m & ((1u << lane) - 1));
            if (pos < EMAXE) g_desc[pos] = make_uint2((unsigned)ls, (unsigned)ld);
            atomicAdd(&g_outdeg[ls], 1);
        }
    }
}

// ---------------- L3: scans + elev normalize + peak seed + CSR fill ----------------
__global__ void __launch_bounds__(256) k_pre(const void* batch, int N) {
    __shared__ int sa[256], sb[256];
    __shared__ int s_cA, s_cB;
    int tid = threadIdx.x;
    int is64 = g_is64;
    int NCH = (N + 255) >> 8;
    for (int ch = blockIdx.x; ch < NCH; ch += gridDim.x) {
        int gid = (ch << 8) + tid;
        int va = 0, vb = 0;
        if (gid < N) { va = g_notpeak[gid] ? 0 : 1; vb = g_outdeg[gid]; }
        sa[tid] = va; sb[tid] = vb; __syncthreads();
        for (int off = 1; off < 256; off <<= 1) {
            int ta = 0, tb = 0;
            if (tid >= off) { ta = sa[tid - off]; tb = sb[tid - off]; }
            __syncthreads();
            if (tid >= off) { sa[tid] += ta; sb[tid] += tb; }
            __syncthreads();
        }
        if (gid < N) { g_peakrank[gid] = sa[tid] - va; g_rowoff[gid] = sb[tid] - vb; }
        if (tid == 255) { g_bsA[ch] = sa[255]; g_bsB[ch] = sb[255]; }
        __syncthreads();
    }
    gbar(&g_barA);
    if (blockIdx.x == 0) {
        if (tid == 0) { s_cA = 0; s_cB = 0; }
        __syncthreads();
        for (int base = 0; base < NCH; base += 256) {
            int i = base + tid;
            int va = (i < NCH) ? g_bsA[i] : 0;
            int vb = (i < NCH) ? g_bsB[i] : 0;
            sa[tid] = va; sb[tid] = vb; __syncthreads();
            for (int off = 1; off < 256; off <<= 1) {
                int ta = 0, tb = 0;
                if (tid >= off) { ta = sa[tid - off]; tb = sb[tid - off]; }
                __syncthreads();
                if (tid >= off) { sa[tid] += ta; sb[tid] += tb; }
                __syncthreads();
            }
            if (i < NCH) { g_bsA[i] = s_cA + sa[tid] - va; g_bsB[i] = s_cB + sb[tid] - vb; }
            __syncthreads();
            if (tid == 0) { s_cA += sa[255]; s_cB += sb[255]; }
            __syncthreads();
        }
        if (tid == 0) {
            g_nP = s_cA;
            g_rowoff[N] = s_cB;
            int P = s_cA; if (P > PMAXP) P = PMAXP;
            g_ptail = P;
        }
    }
    gbar(&g_barA);
    int stride = gridDim.x * 256;
    // S3: finalize rowoff + elev normalize
    for (int n = blockIdx.x * 256 + tid; n < N; n += stride) {
        g_rowoff[n] = g_rowoff[n] + g_bsB[n >> 8];
        long long bt = ld_idx(batch, n, is64);
        if (bt < 0) bt = 0; if (bt >= BMAXB) bt = BMAXB - 1;
        g_e[n] = g_e[n] / g_bsum[bt];
    }
    gbar(&g_barA);
    // S4: peak seed with prefetched row bounds + CSR column fill
    for (int n = blockIdx.x * 256 + tid; n < N; n += stride) {
        if (!g_notpeak[n]) {
            int pr = g_peakrank[n] + g_bsA[n >> 8];
            if (pr < PMAXP) {
                long long bt = ld_idx(batch, n, is64);
                if (bt < 0) bt = 0; if (bt >= BMAXB) bt = BMAXB - 1;
                g_cbv[pr] = (int)bt;
                g_ccount[pr] = 1;
                g_visitcl[n] = (u64)(unsigned)pr;    // level-0 claim
                g_pairs[pr] = make_uint4((unsigned)n, (unsigned)pr,
                                         (unsigned)g_rowoff[n], (unsigned)g_rowoff[n + 1]);
            }
        }
    }
    int D = g_desc_tail; if (D > EMAXE) D = EMAXE;
    for (int e = blockIdx.x * 256 + tid; e < D; e += stride) {
        uint2 ed = g_desc[e];
        int ls = (int)ed.x;
        int pos = g_rowoff[ls] + atomicAdd(&g_fillpos[ls], 1);
        if (pos < EMAXE) g_col[pos] = (int)ed.y;
    }
}

// ---------------- BFS claim decision (no append) ----------------
__device__ __forceinline__ bool claim_dec(int v, unsigned c, int L) {
    u64 mine = ((u64)(unsigned)L << 32) | c;
    u64 cur = g_visitcl[v];                          // load-first (common: already claimed)
    while (true) {
        unsigned curL = (unsigned)(cur >> 32);
        if (curL < (unsigned)L) return false;        // claimed at earlier level
        if (curL == (unsigned)L) {
            if ((unsigned)cur == c) return false;    // duplicate same cluster
            u64 key = ((u64)(unsigned)v << 32) | c;
            u64 h = key * 0x9E3779B97F4A7C15ull;
            h ^= h >> 29; h *= 0xBF58476D1CE4E5B9ull; h ^= h >> 32;
            unsigned slot = (unsigned)h & (HSIZE - 1);
            for (int pb = 0; pb < MAXPROBE; pb++) {
                u64 prev = atomicCAS(&g_htab[slot], HEMPTY, key);
                if (prev == HEMPTY) return true;
                if (prev == key) return false;
                slot = (slot + 1) & (HSIZE - 1);
            }
            return true;                             // probe-exhaust: dup harmless for max
        }
        u64 prev = atomicCAS(&g_visitcl[v], cur, mine);
        if (prev == cur) return true;
        cur = prev;
    }
}

// ---------------- L4: grid-wide level-sync BFS, warp per pair, 148x512 ----------------
__global__ void __launch_bounds__(512) k_bfs() {
    const unsigned FULL = 0xffffffffu;
    int tid = threadIdx.x;
    int lane = tid & 31;
    int gw = (blockIdx.x * (int)blockDim.x + tid) >> 5;
    int nwarps = (gridDim.x * (int)blockDim.x) >> 5;
    int lo = 0;
    int hi = g_nP; if (hi > PMAXP) hi = PMAXP;
    int L = 1;
    while (hi > lo && L < 100000) {
        for (int i = lo + gw; i < hi; i += nwarps) {
            uint4 pr = g_pairs[i];           // broadcast load (v, c, rowbeg, rowend)
            unsigned c = pr.y;
            int beg = (int)pr.z, end = (int)pr.w;
            for (int jb = beg; jb < end; jb += 32) {   // converged chunks
                int j = jb + lane;
                int v = -1;
                bool ins = false;
                if (j < end) {
                    v = g_col[j];
                    ins = claim_dec(v, c, L);
                }
                unsigned m = __ballot_sync(FULL, ins);
                if (m) {
                    int base = 0;
                    if (lane == 0) base = atomicAdd(&g_ptail, __popc(m));
                    base = __shfl_sync(FULL, base, 0);
                    if (ins) {
                        atomicAdd(&g_ccount[c], 1);
                        int pos = base + __popc(m & ((1u << lane) - 1));
                        if (pos < PAIRMAX)
                            g_pairs[pos] = make_uint4((unsigned)v, c,
                                (unsigned)g_rowoff[v], (unsigned)g_rowoff[v + 1]);
                    }
                }
            }
        }
        int nh = gbar_snap(&g_barA);
        lo = hi; hi = nh; L++;
    }
}

// ---------------- L5: scanP + scatter + gather + softmax + outputs (512 thr) ----------------
__global__ void __launch_bounds__(GFT) k_gf(const float* __restrict__ x,
                                            const void* batch,
                                            float* __restrict__ out,
                                            int N, int C) {
    __shared__ int sa[GFT];
    __shared__ int s_cA;
    __shared__ float sred[GFT];
    __shared__ float4 s4[GFT];
    __shared__ int sm_m[GFT];
    int tid = threadIdx.x;
    int P = g_nP; if (P > PMAXP) P = PMAXP;
    int stride = gridDim.x * GFT;
    int NPCH = (P + GFT - 1) / GFT;
    for (int ch = blockIdx.x; ch < NPCH; ch += gridDim.x) {
        int gid = ch * GFT + tid;
        int v = (gid < P) ? g_ccount[gid] : 0;
        sa[tid] = v; __syncthreads();
        for (int off = 1; off < GFT; off <<= 1) {
            int t2 = 0;
            if (tid >= off) t2 = sa[tid - off];
            __syncthreads();
            if (tid >= off) sa[tid] += t2;
            __syncthreads();
        }
        if (gid < P) g_rowP[gid] = sa[tid] - v;
        if (tid == GFT - 1) g_bsA[ch] = sa[GFT - 1];
        __syncthreads();
    }
    gbar(&g_barB);
    if (blockIdx.x == 0) {
        if (tid == 0) s_cA = 0;
        __syncthreads();
        for (int base = 0; base < NPCH; base += GFT) {
            int i = base + tid;
            int v = (i < NPCH) ? g_bsA[i] : 0;
            sa[tid] = v; __syncthreads();
            for (int off = 1; off < GFT; off <<= 1) {
                int t2 = 0;
                if (tid >= off) t2 = sa[tid - off];
                __syncthreads();
                if (tid >= off) sa[tid] += t2;
                __syncthreads();
            }
            if (i < NPCH) g_bsA[i] = s_cA + sa[tid] - v;
            __syncthreads();
            if (tid == 0) s_cA += sa[GFT - 1];
            __syncthreads();
        }
        if (tid == 0) g_rowP[P] = s_cA;
    }
    gbar(&g_barB);
    for (int p = blockIdx.x * GFT + tid; p < P; p += stride) g_rowP[p] += g_bsA[p / GFT];
    gbar(&g_barB);
    int M = g_ptail; if (M > PAIRMAX) M = PAIRMAX;
    for (int i = blockIdx.x * GFT + tid; i < M; i += stride) {
        uint4 pr = g_pairs[i];
        unsigned c = pr.y;
        if (c >= (unsigned)P) continue;
        int pos = g_rowP[c] + atomicAdd(&g_cc2[c], 1);
        if (pos < PAIRMAX) g_mlist[pos] = (int)pr.x;
    }
    gbar(&g_barB);
    int CH4 = C >> 2;
    bool fast = (C % 4 == 0) && CH4 >= 1 && CH4 <= GFT && (GFT % CH4 == 0);
    int MG = fast ? (GFT / CH4) : 1;
    for (int p = blockIdx.x; p < P; p += gridDim.x) {
        int beg = g_rowP[p], end = g_rowP[p + 1];
        float em = -1e30f;
        for (int m = beg + tid; m < end; m += GFT)
            em = fmaxf(em, g_e[g_mlist[m]]);
        sred[tid] = em; __syncthreads();
        for (int off = GFT / 2; off; off >>= 1) {
            if (tid < off) sred[tid] = fmaxf(sred[tid], sred[tid + off]);
            __syncthreads();
        }
        if (tid == 0) g_maxelevF[p] = sred[0];
        if (fast) {
            int mg = tid / CH4, c4 = tid % CH4;
            float4 vm = make_float4(-1e30f, -1e30f, -1e30f, -1e30f);
            const float4* x4 = (const float4*)x;
            #pragma unroll 4
            for (int m = beg + mg; m < end; m += MG) {
                float4 a = x4[(size_t)g_mlist[m] * CH4 + c4];
                vm.x = fmaxf(vm.x, a.x); vm.y = fmaxf(vm.y, a.y);
                vm.z = fmaxf(vm.z, a.z); vm.w = fmaxf(vm.w, a.w);
            }
            s4[tid] = vm; __syncthreads();
            for (int off = MG >> 1; off; off >>= 1) {
                if (mg < off) {
                    float4 o = s4[tid + off * CH4];
                    float4 mvv = s4[tid];
                    mvv.x = fmaxf(mvv.x, o.x); mvv.y = fmaxf(mvv.y, o.y);
                    mvv.z = fmaxf(mvv.z, o.z); mvv.w = fmaxf(mvv.w, o.w);
                    s4[tid] = mvv;
                }
                __syncthreads();
            }
            if (mg == 0) g_pool4[(size_t)p * CH4 + c4] = s4[tid];
        } else {
            float* pm = (float*)g_pool4;
            float vm = -1e30f;
            for (int mb = beg; mb < end; mb += GFT) {
                int cnt = end - mb; if (cnt > GFT) cnt = GFT;
                __syncthreads();
                if (tid < cnt) sm_m[tid] = g_mlist[mb + tid];
                __syncthreads();
                if (tid < C) {
                    for (int j = 0; j < cnt; j++)
                        vm = fmaxf(vm, x[(size_t)sm_m[j] * C + tid]);
                }
            }
            if (tid < C) pm[(size_t)p * C + tid] = vm;
            for (int ch = GFT + tid; ch < C; ch += GFT) {
                float v2 = -1e30f;
                for (int m = beg; m < end; m++)
                    v2 = fmaxf(v2, x[(size_t)g_mlist[m] * C + ch]);
                pm[(size_t)p * C + ch] = v2;
            }
        }
        __syncthreads();
    }
    gbar(&g_barB);
    __shared__ unsigned smax[BMAXB];
    __shared__ float ssum[BMAXB];
    if (tid < BMAXB) smax[tid] = 0u;
    __syncthreads();
    for (int p = blockIdx.x * GFT + tid; p < P; p += stride)
        atomicMax(&smax[g_cbv[p]], encf(g_maxelevF[p]));
    __syncthreads();
    if (tid < BMAXB && smax[tid] != 0u) atomicMax(&g_cbmax[tid], smax[tid]);
    gbar(&g_barB);
    if (tid < BMAXB) ssum[tid] = 0.f;
    __syncthreads();
    for (int p = blockIdx.x * GFT + tid; p < P; p += stride) {
        float ex = expf(g_maxelevF[p] - decf(g_cbmax[g_cbv[p]]));
        g_exn[p] = ex;
        atomicAdd(&ssum[g_cbv[p]], ex);
    }
    __syncthreads();
    if (tid < BMAXB && ssum[tid] != 0.f) atomicAdd(&g_cbsum[tid], ssum[tid]);
    gbar(&g_barB);
    int warp = (blockIdx.x * GFT + tid) >> 5;
    int lane = tid & 31;
    int nw = stride >> 5;
    const float* pm = (const float*)g_pool4;
    for (int p = warp; p < P; p += nw) {
        float normed = g_exn[p] / g_cbsum[g_cbv[p]];
        const float* mx = pm + (size_t)p * C;
        float* orow = out + (size_t)p * C;
        for (int i = lane; i < C; i += 32) orow[i] = mx[i] * normed;
        if (lane == 0) out[(size_t)P * C + p] = (float)g_cbv[p];
    }
    for (int n = blockIdx.x * GFT + tid; n < N; n += stride)
        out[(size_t)P * (C + 1) + n] = g_e[n];
}

// ---------------- host launcher ----------------
extern "C" void kernel_launch(void* const* d_in, const int* in_sizes, int n_in,
                              void* d_out, int out_size) {
    const float* x  = (const float*)d_in[0];
    const void*  ei = d_in[1];
    const void*  bt = d_in[2];
    const float* W  = (const float*)d_in[3];
    const float* bb = (const float*)d_in[4];
    int N = in_sizes[2];
    int C = in_sizes[0] / (N > 0 ? N : 1);
    int E = in_sizes[1] / 2;
    float* out = (float*)d_out;
    cudaStream_t s = 0;

    int gNE = ((N > E ? N : E) + 255) / 256; if (gNE < 1) gNE = 1;
    long long zthreads = (long long)N * 32;
    int gZ = (int)((zthreads + 255) / 256); if (gZ < 1) gZ = 1;

    int sm = 148;
    cudaDeviceGetAttribute(&sm, cudaDevAttrMultiProcessorCount, 0);
    int bpmP = 1, bpmG = 1;
    cudaOccupancyMaxActiveBlocksPerMultiprocessor(&bpmP, k_pre, 256, 0);
    cudaOccupancyMaxActiveBlocksPerMultiprocessor(&bpmG, k_gf, GFT, 0);
    if (bpmP < 1) bpmP = 1;
    if (bpmG < 1) bpmG = 1;
    int nbP = sm * bpmP;
    int nbG = sm * bpmG;
    int nbBFS = sm;   // 1 block/SM, 512 threads

    k_initz<<<gZ, 256, 0, s>>>(x, W, bb, bt, ei, N, C, E);
    k_ee<<<gNE, 256, 0, s>>>(ei, bt, N, E);
    k_pre<<<nbP, 256, 0, s>>>(bt, N);
    k_bfs<<<nbBFS, 512, 0, s>>>();
    k_gf<<<nbG, GFT, 0, s>>>(x, bt, out, N, C);
}

// round 16
// speedup vs baseline: 1.0153x; 1.0153x over previous
#include <cuda_runtime.h>
#include <cstdint>

#define NMAXN   131072
#define EMAXE   2200000
#define PMAXP   32768
#define CMAXC   256
#define BMAXB   64
#define HBITS   20
#define HSIZE   (1u << HBITS)
#define PAIRMAX 2097152
#define HEMPTY  0xFFFFFFFFFFFFFFFFull
#define VUNSET  0xFFFFFFFFFFFFFFFFull
#define MAXPROBE 128
typedef unsigned long long u64;

__device__ float    g_z[NMAXN];
__device__ float    g_e[NMAXN];          // exp -> normalized elev after k_eepre
__device__ int      g_notpeak[NMAXN];
__device__ u64      g_visitcl[NMAXN];    // (level<<32)|cluster of first claim
__device__ int      g_outdeg[NMAXN];
__device__ int      g_rowoff[NMAXN + 1];
__device__ int      g_fillpos[NMAXN];
__device__ int      g_peakrank[NMAXN];
__device__ int      g_col[EMAXE];
__device__ uint2    g_desc[EMAXE];
__device__ uint4    g_pairs[PAIRMAX];    // (v, c, rowbeg, rowend)
__device__ int      g_mlist[PAIRMAX];
__device__ u64      g_htab[HSIZE];
__device__ float4   g_pool4[(size_t)PMAXP * CMAXC / 4];
__device__ float    g_maxelevF[PMAXP];
__device__ int      g_cbv[PMAXP];
__device__ float    g_exn[PMAXP];
__device__ int      g_ccount[PMAXP];
__device__ int      g_cc2[PMAXP];
__device__ int      g_rowP[PMAXP + 1];
__device__ unsigned g_bmaxz[BMAXB];
__device__ float    g_bsum[BMAXB];
__device__ unsigned g_cbmax[BMAXB];
__device__ float    g_cbsum[BMAXB];
__device__ int      g_bsA[1024];
__device__ int      g_bsB[1024];
__device__ int      g_nP;
__device__ int      g_is64;
__device__ int      g_desc_tail;
__device__ int      g_ptail;

struct Bar { int cnt; int gen; int snap; };
__device__ Bar g_barA;
__device__ Bar g_barB;

// ---------------- helpers ----------------
__device__ __forceinline__ unsigned encf(float f) {
    unsigned u = __float_as_uint(f);
    return (u & 0x80000000u) ? ~u : (u | 0x80000000u);
}
__device__ __forceinline__ float decf(unsigned u) {
    return __uint_as_float((u & 0x80000000u) ? (u ^ 0x80000000u) : ~u);
}
__device__ __forceinline__ long long ld_idx(const void* p, long long i, int is64) {
    if (is64) return ((const long long*)p)[i];
    return (long long)((const int*)p)[i];
}
__device__ __forceinline__ void gbar(Bar* b) {
    __syncthreads();
    if (threadIdx.x == 0) {
        __threadfence();
        volatile int* vg = &b->gen;
        int g = *vg;
        if (atomicAdd(&b->cnt, 1) == (int)gridDim.x - 1) {
            b->cnt = 0;
            __threadfence();
            atomicExch(&b->gen, g + 1);
        } else {
            int it = 0;
            while (*vg == g) { if (++it > 4096) { __nanosleep(128); it = 2048; } }
        }
        __threadfence();
    }
    __syncthreads();
}
// barrier + snapshot of g_ptail taken by the releasing block
__device__ __forceinline__ int gbar_snap(Bar* b) {
    __shared__ int s_hi;
    __syncthreads();
    if (threadIdx.x == 0) {
        __threadfence();
        volatile int* vg = &b->gen;
        volatile int* vs = &b->snap;
        int g = *vg;
        if (atomicAdd(&b->cnt, 1) == (int)gridDim.x - 1) {
            int nt = g_ptail; if (nt > PAIRMAX) nt = PAIRMAX;
            *vs = nt;
            b->cnt = 0;
            __threadfence();
            atomicExch(&b->gen, g + 1);
            s_hi = nt;
        } else {
            int it = 0;
            while (*vg == g) { if (++it > 4096) { __nanosleep(128); it = 2048; } }
            __threadfence();
            s_hi = *vs;
        }
        __threadfence();
    }
    __syncthreads();
    return s_hi;
}

// ---------------- L1: init clears + sniff + z + per-batch max ----------------
__global__ void k_initz(const float* __restrict__ x, const float* __restrict__ W,
                        const float* __restrict__ bb, const void* batch,
                        const void* ei, int N, int C, int E) {
    __shared__ unsigned s_bmax[BMAXB];
    __shared__ int s_is64;
    int tid = threadIdx.x;
    if (tid < 32) {
        int nch = E < 8 ? E : 8;
        bool bad = false;
        if (tid < nch) {
            long long v = ((const long long*)ei)[tid];
            bad = (v < 0 || v >= (long long)N);
        }
        unsigned m = __ballot_sync(0xffffffffu, bad);
        if (tid == 0) s_is64 = (m == 0) ? 1 : 0;
    }
    if (tid < BMAXB) s_bmax[tid] = 0u;
    __syncthreads();
    int is64 = s_is64;
    size_t t = (size_t)blockIdx.x * blockDim.x + tid;
    size_t stride = (size_t)gridDim.x * blockDim.x;
    for (size_t i = t; i < HSIZE; i += stride) g_htab[i] = HEMPTY;
    for (size_t i = t; i < (size_t)N; i += stride) {
        g_visitcl[i] = VUNSET; g_notpeak[i] = 0; g_outdeg[i] = 0; g_fillpos[i] = 0;
    }
    for (size_t i = t; i < PMAXP; i += stride) { g_ccount[i] = 0; g_cc2[i] = 0; }
    if (t < BMAXB) { g_bmaxz[t] = 0u; g_bsum[t] = 0.f; g_cbmax[t] = 0u; g_cbsum[t] = 0.f; }
    if (t == 0) {
        g_desc_tail = 0;
        g_barA.cnt = 0; g_barA.gen = 0; g_barA.snap = 0;
        g_barB.cnt = 0; g_barB.gen = 0; g_barB.snap = 0;
        g_is64 = is64;
    }
    // z = x @ W^T + b, warp per node
    int gw = (int)(((size_t)blockIdx.x * blockDim.x + tid) >> 5);
    int lane = tid & 31;
    int nw = (int)(((size_t)gridDim.x * blockDim.x) >> 5);
    int C4 = (C % 4 == 0) ? (C >> 2) : 0;
    for (int n = gw; n < N; n += nw) {
        float acc = 0.f;
        if (C4) {
            const float4* xr = (const float4*)(x + (size_t)n * C);
            const float4* wr = (const float4*)W;
            for (int i = lane; i < C4; i += 32) {
                float4 a = xr[i], w = wr[i];
                acc += a.x * w.x + a.y * w.y + a.z * w.z + a.w * w.w;
            }
        } else {
            for (int i = lane; i < C; i += 32) acc += x[(size_t)n * C + i] * W[i];
        }
        double d = (double)acc;
        #pragma unroll
        for (int o = 16; o; o >>= 1) d += __shfl_down_sync(0xffffffffu, d, o);
        if (lane == 0) {
            float zf = (float)d + bb[0];
            g_z[n] = zf;
            long long bt = ld_idx(batch, n, is64);
            if (bt >= 0 && bt < BMAXB) atomicMax(&s_bmax[bt], encf(zf));
        }
    }
    __syncthreads();
    if (tid < BMAXB && s_bmax[tid] != 0u) atomicMax(&g_bmaxz[tid], s_bmax[tid]);
}

// ---------------- L2 (fused): exp/edges, scans, elev norm, peak seed, CSR fill ----------------
__global__ void __launch_bounds__(256) k_eepre(const void* ei, const void* batch,
                                               int N, int E) {
    __shared__ int sa[256], sb[256];
    __shared__ int s_cA, s_cB;
    __shared__ float ssum[BMAXB];
    int tid = threadIdx.x;
    int is64 = g_is64;
    int stride = gridDim.x * 256;
    // --- ee phase: exp + batch sums ---
    if (tid < BMAXB) ssum[tid] = 0.f;
    __syncthreads();
    for (int n = blockIdx.x * 256 + tid; n < N; n += stride) {
        long long bt = ld_idx(batch, n, is64);
        float ev = expf(g_z[n] - decf(g_bmaxz[bt]));
        g_e[n] = ev;
        atomicAdd(&ssum[bt], ev);
    }
    __syncthreads();
    if (tid < BMAXB && ssum[tid] != 0.f) atomicAdd(&g_bsum[tid], ssum[tid]);
    // --- ee phase: peak flags + descending edge list ---
    for (int e = blockIdx.x * 256 + tid; e < E; e += stride) {
        int ls = (int)ld_idx(ei, e, is64);
        int ld = (int)ld_idx(ei, (long long)E + e, is64);
        float zs = g_z[ls], zd = g_z[ld];
        if (zd < zs) g_notpeak[ld] = 1;
        bool desc = (zd <= zs);
        unsigned m = __ballot_sync(__activemask(), desc);
        if (desc) {
            int lane = tid & 31;
            int leader = __ffs(m) - 1;
            int base = 0;
            if (lane == leader) base = atomicAdd(&g_desc_tail, __popc(m));
            base = __shfl_sync(m, base, leader);
            int pos = base + __popc(m & ((1u << lane) - 1));
            if (pos < EMAXE) g_desc[pos] = make_uint2((unsigned)ls, (unsigned)ld);
            atomicAdd(&g_outdeg[ls], 1);
        }
    }
    gbar(&g_barA);
    // --- pre phase: dual scans ---
    int NCH = (N + 255) >> 8;
    for (int ch = blockIdx.x; ch < NCH; ch += gridDim.x) {
        int gid = (ch << 8) + tid;
        int va = 0, vb = 0;
        if (gid < N) { va = g_notpeak[gid] ? 0 : 1; vb = g_outdeg[gid]; }
        sa[tid] = va; sb[tid] = vb; __syncthreads();
        for (int off = 1; off < 256; off <<= 1) {
            int ta = 0, tb = 0;
            if (tid >= off) { ta = sa[tid - off]; tb = sb[tid - off]; }
            __syncthreads();
            if (tid >= off) { sa[tid] += ta; sb[tid] += tb; }
            __syncthreads();
        }
        if (gid < N) { g_peakrank[gid] = sa[tid] - va; g_rowoff[gid] = sb[tid] - vb; }
        if (tid == 255) { g_bsA[ch] = sa[255]; g_bsB[ch] = sb[255]; }
        __syncthreads();
    }
    gbar(&g_barA);
    if (blockIdx.x == 0) {
        if (tid == 0) { s_cA = 0; s_cB = 0; }
        __syncthreads();
        for (int base = 0; base < NCH; base += 256) {
            int i = base + tid;
            int va = (i < NCH) ? g_bsA[i] : 0;
            int vb = (i < NCH) ? g_bsB[i] : 0;
            sa[tid] = va; sb[tid] = vb; __syncthreads();
            for (int off = 1; off < 256; off <<= 1) {
                int ta = 0, tb = 0;
                if (tid >= off) { ta = sa[tid - off]; tb = sb[tid - off]; }
                __syncthreads();
                if (tid >= off) { sa[tid] += ta; sb[tid] += tb; }
                __syncthreads();
            }
            if (i < NCH) { g_bsA[i] = s_cA + sa[tid] - va; g_bsB[i] = s_cB + sb[tid] - vb; }
            __syncthreads();
            if (tid == 0) { s_cA += sa[255]; s_cB += sb[255]; }
            __syncthreads();
        }
        if (tid == 0) {
            g_nP = s_cA;
            g_rowoff[N] = s_cB;
            int P = s_cA; if (P > PMAXP) P = PMAXP;
            g_ptail = P;
        }
    }
    gbar(&g_barA);
    // S3: finalize rowoff + elev normalize
    for (int n = blockIdx.x * 256 + tid; n < N; n += stride) {
        g_rowoff[n] = g_rowoff[n] + g_bsB[n >> 8];
        long long bt = ld_idx(batch, n, is64);
        if (bt < 0) bt = 0; if (bt >= BMAXB) bt = BMAXB - 1;
        g_e[n] = g_e[n] / g_bsum[bt];
    }
    gbar(&g_barA);
    // S4: peak seed with prefetched row bounds + CSR column fill
    for (int n = blockIdx.x * 256 + tid; n < N; n += stride) {
        if (!g_notpeak[n]) {
            int pr = g_peakrank[n] + g_bsA[n >> 8];
            if (pr < PMAXP) {
                long long bt = ld_idx(batch, n, is64);
                if (bt < 0) bt = 0; if (bt >= BMAXB) bt = BMAXB - 1;
                g_cbv[pr] = (int)bt;
                g_ccount[pr] = 1;
                g_visitcl[n] = (u64)(unsigned)pr;    // level-0 claim
                g_pairs[pr] = make_uint4((unsigned)n, (unsigned)pr,
                                         (unsigned)g_rowoff[n], (unsigned)g_rowoff[n + 1]);
            }
        }
    }
    int D = g_desc_tail; if (D > EMAXE) D = EMAXE;
    for (int e = blockIdx.x * 256 + tid; e < D; e += stride) {
        uint2 ed = g_desc[e];
        int ls = (int)ed.x;
        int pos = g_rowoff[ls] + atomicAdd(&g_fillpos[ls], 1);
        if (pos < EMAXE) g_col[pos] = (int)ed.y;
    }
}

// ---------------- BFS claim decision (no append) ----------------
__device__ __forceinline__ bool claim_dec(int v, unsigned c, int L) {
    u64 mine = ((u64)(unsigned)L << 32) | c;
    u64 cur = g_visitcl[v];                          // load-first (common: already claimed)
    while (true) {
        unsigned curL = (unsigned)(cur >> 32);
        if (curL < (unsigned)L) return false;        // claimed at earlier level
        if (curL == (unsigned)L) {
            if ((unsigned)cur == c) return false;    // duplicate same cluster
            u64 key = ((u64)(unsigned)v << 32) | c;
            u64 h = key * 0x9E3779B97F4A7C15ull;
            h ^= h >> 29; h *= 0xBF58476D1CE4E5B9ull; h ^= h >> 32;
            unsigned slot = (unsigned)h & (HSIZE - 1);
            for (int pb = 0; pb < MAXPROBE; pb++) {
                u64 prev = atomicCAS(&g_htab[slot], HEMPTY, key);
                if (prev == HEMPTY) return true;
                if (prev == key) return false;
                slot = (slot + 1) & (HSIZE - 1);
            }
            return true;                             // probe-exhaust: dup harmless for max
        }
        u64 prev = atomicCAS(&g_visitcl[v], cur, mine);
        if (prev == cur) return true;
        cur = prev;
    }
}

// ---------------- L3: grid-wide level-sync BFS, warp per pair, 148x512 ----------------
__global__ void __launch_bounds__(512) k_bfs() {
    const unsigned FULL = 0xffffffffu;
    int tid = threadIdx.x;
    int lane = tid & 31;
    int gw = (blockIdx.x * (int)blockDim.x + tid) >> 5;
    int nwarps = (gridDim.x * (int)blockDim.x) >> 5;
    int lo = 0;
    int hi = g_nP; if (hi > PMAXP) hi = PMAXP;
    int L = 1;
    while (hi > lo && L < 100000) {
        for (int i = lo + gw; i < hi; i += nwarps) {
            uint4 pr = g_pairs[i];           // broadcast load (v, c, rowbeg, rowend)
            unsigned c = pr.y;
            int beg = (int)pr.z, end = (int)pr.w;
            for (int jb = beg; jb < end; jb += 32) {   // converged chunks
                int j = jb + lane;
                int v = -1;
                bool ins = false;
                if (j < end) {
                    v = g_col[j];
                    ins = claim_dec(v, c, L);
                }
                unsigned m = __ballot_sync(FULL, ins);
                if (m) {
                    int base = 0;
                    if (lane == 0) base = atomicAdd(&g_ptail, __popc(m));
                    base = __shfl_sync(FULL, base, 0);
                    if (ins) {
                        atomicAdd(&g_ccount[c], 1);
                        int pos = base + __popc(m & ((1u << lane) - 1));
                        if (pos < PAIRMAX)
                            g_pairs[pos] = make_uint4((unsigned)v, c,
                                (unsigned)g_rowoff[v], (unsigned)g_rowoff[v + 1]);
                    }
                }
            }
        }
        int nh = gbar_snap(&g_barA);
        lo = hi; hi = nh; L++;
    }
}

// ---------------- L4: scanP + scatter + gather + softmax + outputs ----------------
__global__ void __launch_bounds__(256) k_gf(const float* __restrict__ x,
                                            const void* batch,
                                            float* __restrict__ out,
                                            int N, int C) {
    __shared__ int sa[256];
    __shared__ int s_cA;
    __shared__ float sred[256];
    __shared__ float4 s4[256];
    __shared__ int sm_m[256];
    int tid = threadIdx.x;
    int P = g_nP; if (P > PMAXP) P = PMAXP;
    int stride = gridDim.x * 256;
    int NPCH = (P + 255) >> 8;
    for (int ch = blockIdx.x; ch < NPCH; ch += gridDim.x) {
        int gid = (ch << 8) + tid;
        int v = (gid < P) ? g_ccount[gid] : 0;
        sa[tid] = v; __syncthreads();
        for (int off = 1; off < 256; off <<= 1) {
            int t2 = 0;
            if (tid >= off) t2 = sa[tid - off];
            __syncthreads();
            if (tid >= off) sa[tid] += t2;
            __syncthreads();
        }
        if (gid < P) g_rowP[gid] = sa[tid] - v;
        if (tid == 255) g_bsA[ch] = sa[255];
        __syncthreads();
    }
    gbar(&g_barB);
    if (blockIdx.x == 0) {
        if (tid == 0) s_cA = 0;
        __syncthreads();
        for (int base = 0; base < NPCH; base += 256) {
            int i = base + tid;
            int v = (i < NPCH) ? g_bsA[i] : 0;
            sa[tid] = v; __syncthreads();
            for (int off = 1; off < 256; off <<= 1) {
                int t2 = 0;
                if (tid >= off) t2 = sa[tid - off];
                __syncthreads();
                if (tid >= off) sa[tid] += t2;
                __syncthreads();
            }
            if (i < NPCH) g_bsA[i] = s_cA + sa[tid] - v;
            __syncthreads();
            if (tid == 0) s_cA += sa[255];
            __syncthreads();
        }
        if (tid == 0) g_rowP[P] = s_cA;
    }
    gbar(&g_barB);
    for (int p = blockIdx.x * 256 + tid; p < P; p += stride) g_rowP[p] += g_bsA[p >> 8];
    gbar(&g_barB);
    int M = g_ptail; if (M > PAIRMAX) M = PAIRMAX;
    for (int i = blockIdx.x * 256 + tid; i < M; i += stride) {
        uint4 pr = g_pairs[i];
        unsigned c = pr.y;
        if (c >= (unsigned)P) continue;
        int pos = g_rowP[c] + atomicAdd(&g_cc2[c], 1);
        if (pos < PAIRMAX) g_mlist[pos] = (int)pr.x;
    }
    gbar(&g_barB);
    int CH4 = C >> 2;
    bool fast = (C % 4 == 0) && CH4 >= 1 && CH4 <= 256 && (256 % CH4 == 0);
    int MG = fast ? (256 / CH4) : 1;
    for (int p = blockIdx.x; p < P; p += gridDim.x) {
        int beg = g_rowP[p], end = g_rowP[p + 1];
        float em = -1e30f;
        for (int m = beg + tid; m < end; m += 256)
            em = fmaxf(em, g_e[g_mlist[m]]);
        sred[tid] = em; __syncthreads();
        for (int off = 128; off; off >>= 1) {
            if (tid < off) sred[tid] = fmaxf(sred[tid], sred[tid + off]);
            __syncthreads();
        }
        if (tid == 0) g_maxelevF[p] = sred[0];
        if (fast) {
            int mg = tid / CH4, c4 = tid % CH4;
            float4 vm = make_float4(-1e30f, -1e30f, -1e30f, -1e30f);
            const float4* x4 = (const float4*)x;
            #pragma unroll 4
            for (int m = beg + mg; m < end; m += MG) {
                float4 a = x4[(size_t)g_mlist[m] * CH4 + c4];
                vm.x = fmaxf(vm.x, a.x); vm.y = fmaxf(vm.y, a.y);
                vm.z = fmaxf(vm.z, a.z); vm.w = fmaxf(vm.w, a.w);
            }
            s4[tid] = vm; __syncthreads();
            for (int off = MG >> 1; off; off >>= 1) {
                if (mg < off) {
                    float4 o = s4[tid + off * CH4];
                    float4 mvv = s4[tid];
                    mvv.x = fmaxf(mvv.x, o.x); mvv.y = fmaxf(mvv.y, o.y);
                    mvv.z = fmaxf(mvv.z, o.z); mvv.w = fmaxf(mvv.w, o.w);
                    s4[tid] = mvv;
                }
                __syncthreads();
            }
            if (mg == 0) g_pool4[(size_t)p * CH4 + c4] = s4[tid];
        } else {
            float* pm = (float*)g_pool4;
            float vm = -1e30f;
            for (int mb = beg; mb < end; mb += 256) {
                int cnt = end - mb; if (cnt > 256) cnt = 256;
                __syncthreads();
                if (tid < cnt) sm_m[tid] = g_mlist[mb + tid];
                __syncthreads();
                if (tid < C) {
                    for (int j = 0; j < cnt; j++)
                        vm = fmaxf(vm, x[(size_t)sm_m[j] * C + tid]);
                }
            }
            if (tid < C) pm[(size_t)p * C + tid] = vm;
            for (int ch = 256 + tid; ch < C; ch += 256) {
                float v2 = -1e30f;
                for (int m = beg; m < end; m++)
                    v2 = fmaxf(v2, x[(size_t)g_mlist[m] * C + ch]);
                pm[(size_t)p * C + ch] = v2;
            }
        }
        __syncthreads();
    }
    gbar(&g_barB);
    __shared__ unsigned smax[BMAXB];
    __shared__ float ssum[BMAXB];
    if (tid < BMAXB) smax[tid] = 0u;
    __syncthreads();
    for (int p = blockIdx.x * 256 + tid; p < P; p += stride)
        atomicMax(&smax[g_cbv[p]], encf(g_maxelevF[p]));
    __syncthreads();
    if (tid < BMAXB && smax[tid] != 0u) atomicMax(&g_cbmax[tid], smax[tid]);
    gbar(&g_barB);
    if (tid < BMAXB) ssum[tid] = 0.f;
    __syncthreads();
    for (int p = blockIdx.x * 256 + tid; p < P; p += stride) {
        float ex = expf(g_maxelevF[p] - decf(g_cbmax[g_cbv[p]]));
        g_exn[p] = ex;
        atomicAdd(&ssum[g_cbv[p]], ex);
    }
    __syncthreads();
    if (tid < BMAXB && ssum[tid] != 0.f) atomicAdd(&g_cbsum[tid], ssum[tid]);
    gbar(&g_barB);
    int warp = (blockIdx.x * 256 + tid) >> 5;
    int lane = tid & 31;
    int nw = stride >> 5;
    const float* pm = (const float*)g_pool4;
    for (int p = warp; p < P; p += nw) {
        float normed = g_exn[p] / g_cbsum[g_cbv[p]];
        const float* mx = pm + (size_t)p * C;
        float* orow = out + (size_t)p * C;
        for (int i = lane; i < C; i += 32) orow[i] = mx[i] * normed;
        if (lane == 0) out[(size_t)P * C + p] = (float)g_cbv[p];
    }
    for (int n = blockIdx.x * 256 + tid; n < N; n += stride)
        out[(size_t)P * (C + 1) + n] = g_e[n];
}

// ---------------- host launcher ----------------
extern "C" void kernel_launch(void* const* d_in, const int* in_sizes, int n_in,
                              void* d_out, int out_size) {
    const float* x  = (const float*)d_in[0];
    const void*  ei = d_in[1];
    const void*  bt = d_in[2];
    const float* W  = (const float*)d_in[3];
    const float* bb = (const float*)d_in[4];
    int N = in_sizes[2];
    int C = in_sizes[0] / (N > 0 ? N : 1);
    int E = in_sizes[1] / 2;
    float* out = (float*)d_out;
    cudaStream_t s = 0;

    long long zthreads = (long long)N * 32;
    int gZ = (int)((zthreads + 255) / 256); if (gZ < 1) gZ = 1;

    int sm = 148;
    cudaDeviceGetAttribute(&sm, cudaDevAttrMultiProcessorCount, 0);
    int bpmE = 1, bpmG = 1;
    cudaOccupancyMaxActiveBlocksPerMultiprocessor(&bpmE, k_eepre, 256, 0);
    cudaOccupancyMaxActiveBlocksPerMultiprocessor(&bpmG, k_gf, 256, 0);
    if (bpmE < 1) bpmE = 1;
    if (bpmG < 1) bpmG = 1;
    int nbE = sm * bpmE;
    int nbG = sm * bpmG;
    int nbBFS = sm;   // 1 block/SM, 512 threads

    k_initz<<<gZ, 256, 0, s>>>(x, W, bb, bt, ei, N, C, E);
    k_eepre<<<nbE, 256, 0, s>>>(ei, bt, N, E);
    k_bfs<<<nbBFS, 512, 0, s>>>();
    k_gf<<<nbG, 256, 0, s>>>(x, bt, out, N, C);
}